// round 12
// baseline (speedup 1.0000x reference)
#include <cuda_runtime.h>
#include <cstdint>

#define BB 32
#define QQ 900
#define CCLS 91
#define TT 30
#define BIGV 1e9f
#define RT 16                          // rows per cost-block
#define THR 512
#define RTILES ((QQ + RT - 1) / RT)    // 57

// dynamic SMEM layout (floats):
#define SM_SROW   0                    // RT*QQ tile
#define SM_RB     (SM_SROW + RT * QQ)  // RT float4
#define SM_RX     (SM_RB + RT * 4)
#define SM_RA     (SM_RX + RT * 4)
#define SM_JL     (SM_RA + RT)         // QQ ints (alive list)
#define SM_ALIVE  (SM_JL + QQ)         // 912 bytes -> 228 floats
#define SM_CNT    (SM_ALIVE + 228)
#define SM_TOTALF (SM_CNT + 4)
#define SMEM_BYTES (SM_TOTALF * 4)

// per-row packed pseudo info: keep ? label : -1
__device__ int g_lk[BB * QQ];
// focal class-cost table [B,Q,C] (written by pseudo_kernel, L2-resident)
__device__ float g_cls[BB * QQ * CCLS];

// ---------------------------------------------------------------------------
// Kernel 1: warp-per-row pseudo labels + mask + focal class-cost table.
// Mask GIoU path uses exact IEEE op order (__f*_rn, no FMA contraction):
// a mask flip swaps ~O(10) values for 1e9 across a whole output column.
// ---------------------------------------------------------------------------
__global__ void __launch_bounds__(256)
pseudo_kernel(const float* __restrict__ logits_base,
              const float4* __restrict__ boxes_base,
              const float4* __restrict__ targets,
              const float* __restrict__ pred_logits,
              float* __restrict__ out_mask, int write_mask)
{
    int warp = (blockIdx.x * blockDim.x + threadIdx.x) >> 5;
    int lane = threadIdx.x & 31;
    if (warp >= BB * QQ) return;
    int b = warp / QQ;

    // focal class-cost table for this pred row (fast math, coalesced)
    {
        const float* lrow = pred_logits + (size_t)warp * CCLS;
        float* crow = g_cls + (size_t)warp * CCLS;
        for (int c = lane; c < CCLS; c += 32) {
            float x = lrow[c];
            float e = __expf(-x);
            float p = __fdividef(1.0f, 1.0f + e);
            float omp = 1.0f - p;
            crow[c] = 0.25f * omp * omp * (-__logf(p + 1e-8f))
                    - 0.75f * p * p * (-__logf(omp + 1e-8f));
        }
    }

    // warp argmax over 91 base logits (first-occurrence tie-break)
    const float* row = logits_base + (size_t)warp * CCLS;
    float best = -3.4e38f;
    int bi = 0;
    for (int c = lane; c < CCLS; c += 32) {
        float x = row[c];
        if (x > best) { best = x; bi = c; }
    }
#pragma unroll
    for (int off = 16; off > 0; off >>= 1) {
        float ov = __shfl_down_sync(0xFFFFFFFFu, best, off);
        int   oi = __shfl_down_sync(0xFFFFFFFFu, bi, off);
        if (ov > best || (ov == best && oi < bi)) { best = ov; bi = oi; }
    }
    best = __shfl_sync(0xFFFFFFFFu, best, 0);
    bi   = __shfl_sync(0xFFFFFFFFu, bi, 0);
    int keep = (best > 0.0f);                 // sigmoid(best) > 0.5

    float4 bb = boxes_base[warp];
    float bx0 = __fsub_rn(bb.x, __fmul_rn(0.5f, bb.z));
    float by0 = __fsub_rn(bb.y, __fmul_rn(0.5f, bb.w));
    float bx1 = __fadd_rn(bb.x, __fmul_rn(0.5f, bb.z));
    float by1 = __fadd_rn(bb.y, __fmul_rn(0.5f, bb.w));
    float barea = __fmul_rn(__fsub_rn(bx1, bx0), __fsub_rn(by1, by0));

    int bad = 0;
    if (lane < TT) {
        float4 tb = targets[b * TT + lane];
        float tx0 = __fsub_rn(tb.x, __fmul_rn(0.5f, tb.z));
        float ty0 = __fsub_rn(tb.y, __fmul_rn(0.5f, tb.w));
        float tx1 = __fadd_rn(tb.x, __fmul_rn(0.5f, tb.z));
        float ty1 = __fadd_rn(tb.y, __fmul_rn(0.5f, tb.w));
        float tarea = __fmul_rn(__fsub_rn(tx1, tx0), __fsub_rn(ty1, ty0));

        float lx = fmaxf(bx0, tx0), ly = fmaxf(by0, ty0);
        float rx = fminf(bx1, tx1), ry = fminf(by1, ty1);
        float w = fmaxf(__fsub_rn(rx, lx), 0.0f);
        float h = fmaxf(__fsub_rn(ry, ly), 0.0f);
        float inter = __fmul_rn(w, h);
        float uni = __fsub_rn(__fadd_rn(barea, tarea), inter);
        float iou = __fdiv_rn(inter, uni);

        float clx = fminf(bx0, tx0), cly = fminf(by0, ty0);
        float crx = fmaxf(bx1, tx1), cry = fmaxf(by1, ty1);
        float cw = fmaxf(__fsub_rn(crx, clx), 0.0f);
        float ch = fmaxf(__fsub_rn(cry, cly), 0.0f);
        float ac = __fmul_rn(cw, ch);
        float g = __fsub_rn(iou, __fdiv_rn(__fsub_rn(ac, uni), ac));
        bad = !(-g > -0.1f);
    }
    keep = keep && (__ballot_sync(0xFFFFFFFFu, bad) == 0u);

    if (lane == 0) {
        g_lk[warp] = keep ? bi : -1;
        if (write_mask) out_mask[warp] = keep ? 1.0f : 0.0f;
    }
}

// ---------------------------------------------------------------------------
// Kernel 2: single-pass cost via SMEM staging (no BIG fill, no LUT phase).
// Compaction writes alive list + per-column alive bytes. Pair loop stages
// only alive-column costs into SMEM (dead SMEM left uninitialized). Writeout
// reads staged float4 + 4 alive flags and SELs in BIG for dead columns.
// Every output element written to GMEM exactly once, fully coalesced.
// ---------------------------------------------------------------------------
__global__ void __launch_bounds__(THR)
cost_kernel(const float4* __restrict__ pred_boxes,
            const float4* __restrict__ boxes_base,
            float* __restrict__ out)
{
    extern __shared__ __align__(16) float sm[];
    float*         srow    = sm + SM_SROW;
    float4*        s_rb    = (float4*)(sm + SM_RB);
    float4*        s_rx    = (float4*)(sm + SM_RX);
    float*         s_ra    = sm + SM_RA;
    int*           s_jl    = (int*)(sm + SM_JL);
    unsigned char* s_alive = (unsigned char*)(sm + SM_ALIVE);
    int*           s_cnt   = (int*)(sm + SM_CNT);

    int b  = blockIdx.y;
    int r0 = blockIdx.x * RT;
    int nr = min(RT, QQ - r0);
    int tid = threadIdx.x;

    if (tid == 0) s_cnt[0] = 0;
    if (tid >= 32 && tid - 32 < nr) {
        int r = tid - 32;
        float4 pb = __ldg(&pred_boxes[b * QQ + r0 + r]);
        float hw = 0.5f * pb.z, hh = 0.5f * pb.w;
        float x0 = pb.x - hw, y0 = pb.y - hh;
        float x1 = pb.x + hw, y1 = pb.y + hh;
        s_rb[r] = pb;
        s_rx[r] = make_float4(x0, y0, x1, y1);
        s_ra[r] = (x1 - x0) * (y1 - y0);
    }
    __syncthreads();

    // compaction: alive list + alive bytes (order-free)
    for (int j = tid; j < QQ; j += THR) {
        int lk = __ldg(&g_lk[b * QQ + j]);
        s_alive[j] = (lk >= 0);
        if (lk >= 0) {
            int p = atomicAdd(s_cnt, 1);
            s_jl[p] = j | (lk << 16);
        }
    }
    __syncthreads();
    int nb = s_cnt[0];

    // alive columns: thread owns one column, fills its nr SMEM entries
    const float* clsbase = g_cls + (size_t)(b * QQ + r0) * CCLS;
    for (int s = tid; s < nb; s += THR) {
        int jl = s_jl[s];
        int j = jl & 0xFFFF;
        int lab = jl >> 16;
        float4 jb = __ldg(&boxes_base[b * QQ + j]);
        float jhw = 0.5f * jb.z, jhh = 0.5f * jb.w;
        float jx0 = jb.x - jhw, jy0 = jb.y - jhh;
        float jx1 = jb.x + jhw, jy1 = jb.y + jhh;
        float ja  = (jx1 - jx0) * (jy1 - jy0);

#pragma unroll 4
        for (int r = 0; r < nr; r++) {
            float4 rb = s_rb[r];
            float4 rx = s_rx[r];
            float ra = s_ra[r];

            float l1 = fabsf(rb.x - jb.x) + fabsf(rb.y - jb.y)
                     + fabsf(rb.z - jb.z) + fabsf(rb.w - jb.w);

            float wraw = fminf(rx.z, jx1) - fmaxf(rx.x, jx0);
            float hraw = fminf(rx.w, jy1) - fmaxf(rx.y, jy0);
            float w = fmaxf(wraw, 0.0f);
            float h = fmaxf(hraw, 0.0f);
            float inter = w * h;
            float uni = ra + ja - inter;

            // enclosing box via min+max identity: cw = w_i + w_j - wraw
            float cw = rb.z + jb.z - wraw;
            float ch = rb.w + jb.w - hraw;
            float ac = cw * ch;

            // giou = inter/uni - (ac-uni)/ac = (inter*ac + uni^2 - uni*ac)/(uni*ac)
            float num = fmaf(inter - uni, ac, uni * uni);
            float giou = __fdividef(num, uni * ac);

            float cls = __ldg(clsbase + (size_t)r * CCLS + lab);  // L1-hot

            srow[r * QQ + j] = fmaf(2.0f, cls,
                                    fmaf(5.0f, l1, -2.0f * giou));
        }
    }
    __syncthreads();

    // coalesced writeout with alive-select (dead -> BIG)
    {
        const float4* s4 = (const float4*)srow;
        const int q4 = QQ / 4;                 // 225
        const int n4 = RT * q4;                // 3600
        size_t base = ((size_t)b * QQ + r0) * QQ;
#pragma unroll
        for (int t = tid; t < n4; t += THR) {
            int r = t / q4, c = t - r * q4;
            if (r < nr) {
                float4 v = s4[t];
                uchar4 fl = *(const uchar4*)(s_alive + c * 4);
                v.x = fl.x ? v.x : BIGV;
                v.y = fl.y ? v.y : BIGV;
                v.z = fl.z ? v.z : BIGV;
                v.w = fl.w ? v.w : BIGV;
                *(float4*)(out + base + (size_t)r * QQ + c * 4) = v;
            }
        }
    }
}

extern "C" void kernel_launch(void* const* d_in, const int* in_sizes, int n_in,
                              void* d_out, int out_size)
{
    const float*  pred_logits      = (const float*)d_in[0];
    const float4* pred_boxes       = (const float4*)d_in[1];
    const float*  pred_logits_base = (const float*)d_in[2];
    const float4* pred_boxes_base  = (const float4*)d_in[3];
    const float4* targets_boxes    = (const float4*)d_in[4];
    float* out = (float*)d_out;

    const long long c_elems = (long long)BB * QQ * QQ;
    int write_mask = (out_size >= c_elems + BB * QQ) ? 1 : 0;

    cudaFuncSetAttribute(cost_kernel,
                         cudaFuncAttributeMaxDynamicSharedMemorySize,
                         SMEM_BYTES);

    pseudo_kernel<<<(BB * QQ) / 8, 256>>>(
        pred_logits_base, pred_boxes_base, targets_boxes,
        pred_logits, out + c_elems, write_mask);

    cost_kernel<<<dim3(RTILES, BB), THR, SMEM_BYTES>>>(
        pred_boxes, pred_boxes_base, out);
}